// round 13
// baseline (speedup 1.0000x reference)
#include <cuda_runtime.h>
#include <cuda_bf16.h>
#include <stdint.h>

// Problem dims (fixed by dataset): B=64,S=197 -> M=12608 tokens, D=768, H=3072
#define M_TOK 12608
#define M_PAD 12672           // 99 * 128
#define D_DIM 768
#define H_DIM 3072

// ---------------- scratch (device globals; zero-initialized at load) ----------------
__device__ __align__(256) int8_t g_qx [(size_t)M_PAD * D_DIM];   // pad rows stay 0
__device__ __align__(256) int8_t g_qh [(size_t)M_PAD * H_DIM];   // pad rows stay 0
__device__ __align__(256) int8_t g_qw1[(size_t)H_DIM * D_DIM];
__device__ __align__(256) int8_t g_qw2[(size_t)D_DIM * H_DIM];
__device__ __align__(256) float  g_h  [(size_t)M_TOK * H_DIM];   // fp32 post-GELU hidden
__device__ float    g_sx [M_TOK];
__device__ float    g_sh [M_TOK];
__device__ unsigned g_wamax[2];                     // zero-init; atomicMax idempotent

// ---------------- helpers ----------------
__device__ __forceinline__ float warpMax(float v) {
#pragma unroll
    for (int o = 16; o > 0; o >>= 1) v = fmaxf(v, __shfl_xor_sync(0xffffffffu, v, o));
    return v;
}

__device__ __forceinline__ float gelu_exact(float v) {
    return 0.5f * v * (1.0f + erff(v * 0.7071067811865475f));
}

__device__ __forceinline__ void cp16(void* sm, const void* gm) {
    unsigned a = (unsigned)__cvta_generic_to_shared(sm);
    asm volatile("cp.async.cg.shared.global [%0], [%1], 16;" :: "r"(a), "l"(gm));
}

// ---------------- small kernels: SCALAR access to harness pointers (proven R7 shape) ----------------
__global__ void wamax_kernel(const float* __restrict__ w, int n, int slot) {
    float m = 0.f;
    for (int i = blockIdx.x * blockDim.x + threadIdx.x; i < n; i += gridDim.x * blockDim.x)
        m = fmaxf(m, fabsf(w[i]));
    __shared__ float sh[8];
    int lane = threadIdx.x & 31, wid = threadIdx.x >> 5;
    m = warpMax(m);
    if (lane == 0) sh[wid] = m;
    __syncthreads();
    if (threadIdx.x == 0) {
        float t = sh[0];
#pragma unroll
        for (int i = 1; i < 8; i++) t = fmaxf(t, sh[i]);
        atomicMax(&g_wamax[slot], __float_as_uint(t));
    }
}

template <int PHASE>
__global__ void quant_w_kernel(const float* __restrict__ w, int n) {
    int8_t* qw = (PHASE == 0) ? g_qw1 : g_qw2;
    float s = fmaxf(__uint_as_float(g_wamax[PHASE]), 1e-6f) / 127.0f;
    for (int i = blockIdx.x * blockDim.x + threadIdx.x; i < n; i += gridDim.x * blockDim.x)
        qw[i] = (int8_t)__float2int_rn(w[i] / s);       // exact int in [-127,127]
}

__global__ void quant_x_kernel(const float* __restrict__ x) {
    int row = blockIdx.x;
    const float* xr = x + (size_t)row * D_DIM;
    float m = 0.f;
    for (int i = threadIdx.x; i < D_DIM; i += 256) m = fmaxf(m, fabsf(xr[i]));
    __shared__ float sh[8];
    __shared__ float s_bcast;
    int lane = threadIdx.x & 31, wid = threadIdx.x >> 5;
    m = warpMax(m);
    if (lane == 0) sh[wid] = m;
    __syncthreads();
    if (threadIdx.x == 0) {
        float t = sh[0];
#pragma unroll
        for (int i = 1; i < 8; i++) t = fmaxf(t, sh[i]);
        float s = fmaxf(t, 1e-6f) / 127.0f;
        s_bcast = s;
        g_sx[row] = s;
    }
    __syncthreads();
    float s = s_bcast;
    int8_t* q = g_qx + (size_t)row * D_DIM;
    for (int i = threadIdx.x; i < D_DIM; i += 256) q[i] = (int8_t)__float2int_rn(xr[i] / s);
}

__global__ void quant_h_kernel() {
    int row = blockIdx.x;
    const float* hr = g_h + (size_t)row * H_DIM;
    float m = 0.f;
    for (int i = threadIdx.x; i < H_DIM; i += 256) m = fmaxf(m, fabsf(hr[i]));
    __shared__ float sh[8];
    __shared__ float s_bcast;
    int lane = threadIdx.x & 31, wid = threadIdx.x >> 5;
    m = warpMax(m);
    if (lane == 0) sh[wid] = m;
    __syncthreads();
    if (threadIdx.x == 0) {
        float t = sh[0];
#pragma unroll
        for (int i = 1; i < 8; i++) t = fmaxf(t, sh[i]);
        float s = fmaxf(t, 1e-6f) / 127.0f;
        s_bcast = s;
        g_sh[row] = s;
    }
    __syncthreads();
    float s = s_bcast;
    int8_t* q = g_qh + (size_t)row * H_DIM;
    for (int i = threadIdx.x; i < H_DIM; i += 256) q[i] = (int8_t)__float2int_rn(hr[i] / s);
}

// ---------------- int8 GEMM: C[M,N] = A[M,K] @ B[N,K]^T, s8 in, s32 acc ----------------
// R9-proven skeleton: block 128x128, 8 warps (2x4), warp tile 64x32,
// 3-stage cp.async pipeline, ONE __syncthreads per k-tile.
// NEW (single variable): mma.sync.m16n8k32.s8 + int8 tile (BK=128 int8 = 128B rows).
#define BM 128
#define BN 128
#define BK 128                        // int8 elements per k-tile (128 bytes)
#define SROW 144                      // row stride: banks (36g + q) mod 32 all distinct
#define STAGE_B (2 * BM * SROW)       // 36864 B
#define GSMEM   (3 * STAGE_B)         // 110592 B

template <bool GELU, int PHASE>
__global__ void __launch_bounds__(256, 2) gemm_kernel(const float* __restrict__ bias,
                                                      float* __restrict__ Cout, int M) {
    const int N = (PHASE == 0) ? H_DIM : D_DIM;
    const int K = (PHASE == 0) ? D_DIM : H_DIM;
    const int8_t* __restrict__ A = (PHASE == 0) ? g_qx : g_qh;
    const int8_t* __restrict__ B = (PHASE == 0) ? g_qw1 : g_qw2;
    const float* __restrict__ rowscale = (PHASE == 0) ? g_sx : g_sh;
    float* __restrict__ C              = (PHASE == 0) ? g_h : Cout;

    extern __shared__ __align__(128) char dsm[];

    const int tid  = threadIdx.x;
    const int lane = tid & 31, warp = tid >> 5;
    const int wm = warp & 1, wn = warp >> 1;   // 2 warps in M, 4 in N
    const int bm = blockIdx.y * BM, bn = blockIdx.x * BN;

    int acc[4][4][4];
#pragma unroll
    for (int i = 0; i < 4; i++)
#pragma unroll
        for (int j = 0; j < 4; j++)
#pragma unroll
            for (int r = 0; r < 4; r++) acc[i][j][r] = 0;

    auto tileA = [&](int st) { return (int8_t*)(dsm + st * STAGE_B); };
    auto tileB = [&](int st) { return (int8_t*)(dsm + st * STAGE_B + BM * SROW); };

    auto load_stage = [&](int st, int k0) {
        int8_t* sA = tileA(st);
        int8_t* sB = tileB(st);
#pragma unroll
        for (int j = 0; j < 8; j++) {                // 2048 chunks of 16B
            int idx = tid + j * 256;
            int r = (idx >> 3) & 127, c = idx & 7;   // 8 chunks of 16B per 128B row
            bool isA = idx < 1024;
            const int8_t* src = (isA ? A + (size_t)(bm + r) * K
                                     : B + (size_t)(bn + r) * K) + k0 + c * 16;
            int8_t* dst = (isA ? sA : sB) + r * SROW + c * 16;
            cp16(dst, src);
        }
        asm volatile("cp.async.commit_group;");
    };

    const int ktiles = K / BK;
    load_stage(0, 0);
    load_stage(1, BK);

    const int g  = lane >> 2;            // fragment group row
    const int t4 = (lane & 3) * 4;       // byte offset within k-quad
    const int lc = (lane & 3) * 2;       // epilogue column offset

    for (int kt = 0; kt < ktiles; ++kt) {
        asm volatile("cp.async.wait_group 1;" ::: "memory");
        __syncthreads();

        if (kt + 2 < ktiles) load_stage((kt + 2) % 3, (kt + 2) * BK);
        else asm volatile("cp.async.commit_group;");   // empty group keeps count aligned

        const int st = kt % 3;
        const int8_t* sA = tileA(st);
        const int8_t* sB = tileB(st);

#pragma unroll
        for (int ks = 0; ks < BK; ks += 32) {          // 4 x k32 groups
            uint32_t af[4][4], bf[4][2];
#pragma unroll
            for (int mi = 0; mi < 4; mi++) {
                const int8_t* p = sA + (wm * 64 + mi * 16 + g) * SROW + ks + t4;
                af[mi][0] = *(const uint32_t*)(p);                 // row g,   k 0..3 of quad
                af[mi][1] = *(const uint32_t*)(p + 8 * SROW);      // row g+8
                af[mi][2] = *(const uint32_t*)(p + 16);            // row g,   k 16..19
                af[mi][3] = *(const uint32_t*)(p + 8 * SROW + 16); // row g+8, k 16..19
            }
#pragma unroll
            for (int ni = 0; ni < 4; ni++) {
                const int8_t* p = sB + (wn * 32 + ni * 8 + g) * SROW + ks + t4;
                bf[ni][0] = *(const uint32_t*)(p);
                bf[ni][1] = *(const uint32_t*)(p + 16);
            }
#pragma unroll
            for (int mi = 0; mi < 4; mi++)
#pragma unroll
                for (int ni = 0; ni < 4; ni++) {
                    asm volatile(
                        "mma.sync.aligned.m16n8k32.row.col.s32.s8.s8.s32 "
                        "{%0,%1,%2,%3}, {%4,%5,%6,%7}, {%8,%9}, {%0,%1,%2,%3};"
                        : "+r"(acc[mi][ni][0]), "+r"(acc[mi][ni][1]),
                          "+r"(acc[mi][ni][2]), "+r"(acc[mi][ni][3])
                        : "r"(af[mi][0]), "r"(af[mi][1]), "r"(af[mi][2]), "r"(af[mi][3]),
                          "r"(bf[ni][0]), "r"(bf[ni][1]));
                }
        }
    }
    asm volatile("cp.async.wait_group 0;" ::: "memory");   // drain before exit

    // epilogue: (float(isum) + bias) * (rowscale * sw)  [+ exact GELU]; SCALAR stores
    const float sw = fmaxf(__uint_as_float(g_wamax[PHASE]), 1e-6f) / 127.0f;
#pragma unroll
    for (int mi = 0; mi < 4; mi++) {
#pragma unroll
        for (int h = 0; h < 2; h++) {
            int row = bm + wm * 64 + mi * 16 + g + h * 8;
            if (row < M) {
                float rs = rowscale[row] * sw;
#pragma unroll
                for (int ni = 0; ni < 4; ni++) {
                    int col = bn + wn * 32 + ni * 8 + lc;
                    float v0 = ((float)acc[mi][ni][h * 2 + 0] + bias[col    ]) * rs;
                    float v1 = ((float)acc[mi][ni][h * 2 + 1] + bias[col + 1]) * rs;
                    if (GELU) { v0 = gelu_exact(v0); v1 = gelu_exact(v1); }
                    C[(size_t)row * N + col    ] = v0;
                    C[(size_t)row * N + col + 1] = v1;
                }
            }
        }
    }
}

// ---------------- launch ----------------
// ncu -s 5 has a +2 harness-launch offset -> profiles MY index 3 (gemm1).
extern "C" void kernel_launch(void* const* d_in, const int* in_sizes, int n_in,
                              void* d_out, int out_size) {
    const float* x  = (const float*)d_in[0];
    const float* w1 = (const float*)d_in[1];
    const float* b1 = (const float*)d_in[2];
    const float* w2 = (const float*)d_in[3];
    const float* b2 = (const float*)d_in[4];
    const int M = in_sizes[0] / D_DIM;   // 12608

    cudaFuncSetAttribute(gemm_kernel<true, 0>,
                         cudaFuncAttributeMaxDynamicSharedMemorySize, GSMEM);
    cudaFuncSetAttribute(gemm_kernel<false, 1>,
                         cudaFuncAttributeMaxDynamicSharedMemorySize, GSMEM);

    wamax_kernel<<<1024, 256>>>(w1, in_sizes[1], 0);           // 0
    quant_w_kernel<0><<<2048, 256>>>(w1, in_sizes[1]);         // 1
    quant_x_kernel<<<M, 256>>>(x);                             // 2

    dim3 g1(H_DIM / BN, (M + BM - 1) / BM);
    gemm_kernel<true, 0><<<g1, 256, GSMEM>>>(b1, nullptr, M);  // 3  <- ncu target

    wamax_kernel<<<1024, 256>>>(w2, in_sizes[3], 1);           // 4
    quant_w_kernel<1><<<2048, 256>>>(w2, in_sizes[3]);         // 5
    quant_h_kernel<<<M, 256>>>();                              // 6

    dim3 g2(D_DIM / BN, (M + BM - 1) / BM);
    gemm_kernel<false, 1><<<g2, 256, GSMEM>>>(b2, (float*)d_out, M);  // 7
}

// round 14
// speedup vs baseline: 1.9781x; 1.9781x over previous
#include <cuda_runtime.h>
#include <cuda_bf16.h>
#include <stdint.h>

// Problem dims (fixed by dataset): B=64,S=197 -> M=12608 tokens, D=768, H=3072
#define M_TOK 12608
#define M_PAD 12672           // 99 * 128
#define D_DIM 768
#define H_DIM 3072

// ---------------- scratch (device globals; zero-initialized at load) ----------------
// All explicitly 256B-aligned: vector access is allowed ONLY on these.
__device__ __align__(256) __nv_bfloat16 g_qx [(size_t)M_PAD * D_DIM];   // pad rows stay 0
__device__ __align__(256) __nv_bfloat16 g_qh [(size_t)M_PAD * H_DIM];   // pad rows stay 0
__device__ __align__(256) __nv_bfloat16 g_qw1[(size_t)H_DIM * D_DIM];
__device__ __align__(256) __nv_bfloat16 g_qw2[(size_t)D_DIM * H_DIM];
__device__ __align__(256) float         g_h  [(size_t)M_TOK * H_DIM];   // fp32 post-GELU hidden
__device__ float         g_sx [M_TOK];
__device__ float         g_sh [M_TOK];
__device__ unsigned      g_wamax[2];              // zero-init; atomicMax idempotent

// ---------------- helpers ----------------
__device__ __forceinline__ float warpMax(float v) {
#pragma unroll
    for (int o = 16; o > 0; o >>= 1) v = fmaxf(v, __shfl_xor_sync(0xffffffffu, v, o));
    return v;
}

__device__ __forceinline__ float gelu_exact(float v) {
    return 0.5f * v * (1.0f + erff(v * 0.7071067811865475f));
}

__device__ __forceinline__ void cp16(void* sm, const void* gm) {
    unsigned a = (unsigned)__cvta_generic_to_shared(sm);
    asm volatile("cp.async.cg.shared.global [%0], [%1], 16;" :: "r"(a), "l"(gm));
}

// ---------------- elementwise kernels ----------------
// RULE: harness pointers (w, x, bias, d_out) -> SCALAR access only.
//       my aligned globals (g_*) -> vector access OK.

__global__ void wamax_kernel(const float* __restrict__ w, int n, int slot) {
    float m = 0.f;
    for (int i = blockIdx.x * blockDim.x + threadIdx.x; i < n; i += gridDim.x * blockDim.x)
        m = fmaxf(m, fabsf(w[i]));                 // scalar harness reads
    __shared__ float sh[8];
    int lane = threadIdx.x & 31, wid = threadIdx.x >> 5;
    m = warpMax(m);
    if (lane == 0) sh[wid] = m;
    __syncthreads();
    if (threadIdx.x == 0) {
        float t = sh[0];
#pragma unroll
        for (int i = 1; i < 8; i++) t = fmaxf(t, sh[i]);
        atomicMax(&g_wamax[slot], __float_as_uint(t));
    }
}

template <int PHASE>
__global__ void quant_w_kernel(const float* __restrict__ w, int n2) {
    __nv_bfloat16* qw = (PHASE == 0) ? g_qw1 : g_qw2;
    const float s = fmaxf(__uint_as_float(g_wamax[PHASE]), 1e-6f) / 127.0f;
    __nv_bfloat162* q2 = (__nv_bfloat162*)qw;      // mine: 4B stores OK
    for (int i = blockIdx.x * blockDim.x + threadIdx.x; i < n2; i += gridDim.x * blockDim.x) {
        float a = w[2 * i], b = w[2 * i + 1];      // scalar harness reads
        __nv_bfloat162 v;
        v.x = __float2bfloat16(rintf(a / s));
        v.y = __float2bfloat16(rintf(b / s));
        q2[i] = v;
    }
}

__global__ void quant_x_kernel(const float* __restrict__ x) {
    int row = blockIdx.x;
    const float* xr = x + (size_t)row * D_DIM;
    float m = 0.f;
    for (int i = threadIdx.x; i < D_DIM; i += 256) m = fmaxf(m, fabsf(xr[i]));  // scalar
    __shared__ float sh[8];
    __shared__ float s_bcast;
    int lane = threadIdx.x & 31, wid = threadIdx.x >> 5;
    m = warpMax(m);
    if (lane == 0) sh[wid] = m;
    __syncthreads();
    if (threadIdx.x == 0) {
        float t = sh[0];
#pragma unroll
        for (int i = 1; i < 8; i++) t = fmaxf(t, sh[i]);
        float s = fmaxf(t, 1e-6f) / 127.0f;
        s_bcast = s;
        g_sx[row] = s;
    }
    __syncthreads();
    float s = s_bcast;
    __nv_bfloat162* q2 = (__nv_bfloat162*)(g_qx + (size_t)row * D_DIM);   // mine
    for (int i = threadIdx.x; i < D_DIM / 2; i += 256) {
        float a = xr[2 * i], b = xr[2 * i + 1];    // scalar harness reads
        __nv_bfloat162 v;
        v.x = __float2bfloat16(rintf(a / s));
        v.y = __float2bfloat16(rintf(b / s));
        q2[i] = v;
    }
}

__global__ void quant_h_kernel() {
    int row = blockIdx.x;
    const float4* hr4 = (const float4*)(g_h + (size_t)row * H_DIM);       // mine: float4 OK
    float m = 0.f;
    for (int i = threadIdx.x; i < H_DIM / 4; i += 256) {
        float4 v = hr4[i];
        m = fmaxf(m, fmaxf(fmaxf(fabsf(v.x), fabsf(v.y)), fmaxf(fabsf(v.z), fabsf(v.w))));
    }
    __shared__ float sh[8];
    __shared__ float s_bcast;
    int lane = threadIdx.x & 31, wid = threadIdx.x >> 5;
    m = warpMax(m);
    if (lane == 0) sh[wid] = m;
    __syncthreads();
    if (threadIdx.x == 0) {
        float t = sh[0];
#pragma unroll
        for (int i = 1; i < 8; i++) t = fmaxf(t, sh[i]);
        float s = fmaxf(t, 1e-6f) / 127.0f;
        s_bcast = s;
        g_sh[row] = s;
    }
    __syncthreads();
    float s = s_bcast;
    uint2* q4 = (uint2*)(g_qh + (size_t)row * H_DIM);                     // mine: 8B stores OK
    for (int i = threadIdx.x; i < H_DIM / 4; i += 256) {
        float4 v = hr4[i];
        __nv_bfloat162 lo, hi;
        lo.x = __float2bfloat16(rintf(v.x / s));
        lo.y = __float2bfloat16(rintf(v.y / s));
        hi.x = __float2bfloat16(rintf(v.z / s));
        hi.y = __float2bfloat16(rintf(v.w / s));
        uint2 o;
        o.x = *(uint32_t*)&lo;
        o.y = *(uint32_t*)&hi;
        q4[i] = o;
    }
}

// ---------------- GEMM: R9-champion mainloop, byte-identical ----------------
// block tile 128x128x64, 8 warps (2x4), warp tile 64x32, mma.sync m16n8k16.
// 3-stage cp.async pipeline, ONE __syncthreads per k-tile.
#define BM 128
#define BN 128
#define BK 64
#define SK 72                   // row stride 144B: conflict-free fragment LDS
#define STAGE_B (2 * BM * SK * 2)     // 36864 B
#define GSMEM   (3 * STAGE_B)         // 110592 B

template <bool GELU, int PHASE>
__global__ void __launch_bounds__(256, 2) gemm_kernel(const float* __restrict__ bias,
                                                      float* __restrict__ Cout, int M) {
    const int N = (PHASE == 0) ? H_DIM : D_DIM;
    const int K = (PHASE == 0) ? D_DIM : H_DIM;
    const __nv_bfloat16* __restrict__ A = (PHASE == 0) ? g_qx : g_qh;
    const __nv_bfloat16* __restrict__ B = (PHASE == 0) ? g_qw1 : g_qw2;
    const float* __restrict__ rowscale  = (PHASE == 0) ? g_sx : g_sh;
    float* __restrict__ C               = (PHASE == 0) ? g_h : Cout;

    extern __shared__ __align__(128) char dsm[];

    const int tid  = threadIdx.x;
    const int lane = tid & 31, warp = tid >> 5;
    const int wm = warp & 1, wn = warp >> 1;   // 2 warps in M, 4 in N
    const int bm = blockIdx.y * BM, bn = blockIdx.x * BN;

    float acc[4][4][4];
#pragma unroll
    for (int i = 0; i < 4; i++)
#pragma unroll
        for (int j = 0; j < 4; j++)
#pragma unroll
            for (int r = 0; r < 4; r++) acc[i][j][r] = 0.f;

    auto tileA = [&](int st) { return (__nv_bfloat16*)(dsm + st * STAGE_B); };
    auto tileB = [&](int st) { return (__nv_bfloat16*)(dsm + st * STAGE_B + BM * SK * 2); };

    auto load_stage = [&](int st, int k0) {
        __nv_bfloat16* sA = tileA(st);
        __nv_bfloat16* sB = tileB(st);
#pragma unroll
        for (int j = 0; j < 8; j++) {                // 2048 chunks of 16B
            int idx = tid + j * 256;
            int r = (idx >> 3) & 127, c = idx & 7;   // 8 chunks of 8 bf16 per 64-wide row
            bool isA = idx < 1024;
            const __nv_bfloat16* src = (isA ? A + (size_t)(bm + r) * K
                                            : B + (size_t)(bn + r) * K) + k0 + c * 8;
            __nv_bfloat16* dst = (isA ? sA : sB) + r * SK + c * 8;
            cp16(dst, src);
        }
        asm volatile("cp.async.commit_group;");
    };

    const int ktiles = K / BK;
    load_stage(0, 0);
    load_stage(1, BK);

    const int lrow = lane >> 2;
    const int lcol = (lane & 3) << 1;

    for (int kt = 0; kt < ktiles; ++kt) {
        asm volatile("cp.async.wait_group 1;" ::: "memory");
        __syncthreads();

        if (kt + 2 < ktiles) load_stage((kt + 2) % 3, (kt + 2) * BK);
        else asm volatile("cp.async.commit_group;");   // empty group keeps count aligned

        const int st = kt % 3;
        const __nv_bfloat16* sA = tileA(st);
        const __nv_bfloat16* sB = tileB(st);

#pragma unroll
        for (int kk = 0; kk < BK; kk += 16) {
            uint32_t af[4][4], bf[4][2];
#pragma unroll
            for (int mi = 0; mi < 4; mi++) {
                int r = wm * 64 + mi * 16 + lrow;
                af[mi][0] = *(const uint32_t*)&sA[(r    ) * SK + kk     + lcol];
                af[mi][1] = *(const uint32_t*)&sA[(r + 8) * SK + kk     + lcol];
                af[mi][2] = *(const uint32_t*)&sA[(r    ) * SK + kk + 8 + lcol];
                af[mi][3] = *(const uint32_t*)&sA[(r + 8) * SK + kk + 8 + lcol];
            }
#pragma unroll
            for (int ni = 0; ni < 4; ni++) {
                int r = wn * 32 + ni * 8 + lrow;
                bf[ni][0] = *(const uint32_t*)&sB[r * SK + kk     + lcol];
                bf[ni][1] = *(const uint32_t*)&sB[r * SK + kk + 8 + lcol];
            }
#pragma unroll
            for (int mi = 0; mi < 4; mi++)
#pragma unroll
                for (int ni = 0; ni < 4; ni++) {
                    asm volatile(
                        "mma.sync.aligned.m16n8k16.row.col.f32.bf16.bf16.f32 "
                        "{%0,%1,%2,%3}, {%4,%5,%6,%7}, {%8,%9}, {%0,%1,%2,%3};"
                        : "+f"(acc[mi][ni][0]), "+f"(acc[mi][ni][1]),
                          "+f"(acc[mi][ni][2]), "+f"(acc[mi][ni][3])
                        : "r"(af[mi][0]), "r"(af[mi][1]), "r"(af[mi][2]), "r"(af[mi][3]),
                          "r"(bf[ni][0]), "r"(bf[ni][1]));
                }
        }
    }
    asm volatile("cp.async.wait_group 0;" ::: "memory");   // drain before exit

    // epilogue: (acc + bias) * (rowscale * sw)  [+ exact GELU]
    // PHASE 0 -> g_h (mine): float2 stores.  PHASE 1 -> d_out (harness): scalar stores.
    const float sw = fmaxf(__uint_as_float(g_wamax[PHASE]), 1e-6f) / 127.0f;
#pragma unroll
    for (int mi = 0; mi < 4; mi++) {
#pragma unroll
        for (int h = 0; h < 2; h++) {
            int row = bm + wm * 64 + mi * 16 + lrow + h * 8;
            if (row < M) {
                float rs = rowscale[row] * sw;
#pragma unroll
                for (int ni = 0; ni < 4; ni++) {
                    int col = bn + wn * 32 + ni * 8 + lcol;
                    float v0 = (acc[mi][ni][h * 2 + 0] + bias[col    ]) * rs;
                    float v1 = (acc[mi][ni][h * 2 + 1] + bias[col + 1]) * rs;
                    if (GELU) { v0 = gelu_exact(v0); v1 = gelu_exact(v1); }
                    if (PHASE == 0) {
                        float2 o = {v0, v1};
                        *(float2*)(C + (size_t)row * N + col) = o;   // g_h: 8B-aligned
                    } else {
                        C[(size_t)row * N + col    ] = v0;           // d_out: scalar
                        C[(size_t)row * N + col + 1] = v1;
                    }
                }
            }
        }
    }
}

// ---------------- launch ----------------
// ncu -s 5 has a +2 harness-launch offset -> profiles MY index 3 (gemm1).
extern "C" void kernel_launch(void* const* d_in, const int* in_sizes, int n_in,
                              void* d_out, int out_size) {
    const float* x  = (const float*)d_in[0];
    const float* w1 = (const float*)d_in[1];
    const float* b1 = (const float*)d_in[2];
    const float* w2 = (const float*)d_in[3];
    const float* b2 = (const float*)d_in[4];
    const int M = in_sizes[0] / D_DIM;   // 12608

    cudaFuncSetAttribute(gemm_kernel<true, 0>,
                         cudaFuncAttributeMaxDynamicSharedMemorySize, GSMEM);
    cudaFuncSetAttribute(gemm_kernel<false, 1>,
                         cudaFuncAttributeMaxDynamicSharedMemorySize, GSMEM);

    wamax_kernel<<<1024, 256>>>(w1, in_sizes[1], 0);           // 0
    quant_w_kernel<0><<<2048, 256>>>(w1, in_sizes[1] / 2);     // 1
    quant_x_kernel<<<M, 256>>>(x);                             // 2

    dim3 g1(H_DIM / BN, (M + BM - 1) / BM);
    gemm_kernel<true, 0><<<g1, 256, GSMEM>>>(b1, nullptr, M);  // 3  <- ncu target

    wamax_kernel<<<1024, 256>>>(w2, in_sizes[3], 1);           // 4
    quant_w_kernel<1><<<2048, 256>>>(w2, in_sizes[3] / 2);     // 5
    quant_h_kernel<<<M, 256>>>();                              // 6

    dim3 g2(D_DIM / BN, (M + BM - 1) / BM);
    gemm_kernel<false, 1><<<g2, 256, GSMEM>>>(b2, (float*)d_out, M);  // 7
}

// round 15
// speedup vs baseline: 2.0485x; 1.0356x over previous
#include <cuda_runtime.h>
#include <cuda_bf16.h>
#include <stdint.h>

// Problem dims (fixed by dataset): B=64,S=197 -> M=12608 tokens, D=768, H=3072
#define M_TOK 12608
#define M_PAD 12672           // 99 * 128
#define D_DIM 768
#define H_DIM 3072

// ---------------- scratch (device globals; zero-initialized at load) ----------------
// Vector access allowed ONLY on these aligned globals; harness pointers stay scalar.
__device__ __align__(256) __nv_bfloat16 g_qx [(size_t)M_PAD * D_DIM];   // pad rows stay 0
__device__ __align__(256) __nv_bfloat16 g_qh [(size_t)M_PAD * H_DIM];   // pad rows stay 0
__device__ __align__(256) __nv_bfloat16 g_qw1[(size_t)H_DIM * D_DIM];
__device__ __align__(256) __nv_bfloat16 g_qw2[(size_t)D_DIM * H_DIM];
__device__ __align__(256) float         g_h  [(size_t)M_TOK * H_DIM];   // fp32 post-GELU hidden
__device__ float         g_sx [M_TOK];
__device__ float         g_sh [M_TOK];
__device__ unsigned      g_wamax[2];              // zero-init; atomicMax idempotent

// ---------------- helpers ----------------
__device__ __forceinline__ float warpMax(float v) {
#pragma unroll
    for (int o = 16; o > 0; o >>= 1) v = fmaxf(v, __shfl_xor_sync(0xffffffffu, v, o));
    return v;
}

__device__ __forceinline__ float gelu_exact(float v) {
    return 0.5f * v * (1.0f + erff(v * 0.7071067811865475f));
}

__device__ __forceinline__ void cp16(void* sm, const void* gm) {
    unsigned a = (unsigned)__cvta_generic_to_shared(sm);
    asm volatile("cp.async.cg.shared.global [%0], [%1], 16;" :: "r"(a), "l"(gm));
}

__device__ __forceinline__ uint32_t s2u(const void* p) {
    return (uint32_t)__cvta_generic_to_shared(p);
}

// ---------------- elementwise kernels (R14-proven, unchanged) ----------------
__global__ void wamax_kernel(const float* __restrict__ w, int n, int slot) {
    float m = 0.f;
    for (int i = blockIdx.x * blockDim.x + threadIdx.x; i < n; i += gridDim.x * blockDim.x)
        m = fmaxf(m, fabsf(w[i]));                 // scalar harness reads
    __shared__ float sh[8];
    int lane = threadIdx.x & 31, wid = threadIdx.x >> 5;
    m = warpMax(m);
    if (lane == 0) sh[wid] = m;
    __syncthreads();
    if (threadIdx.x == 0) {
        float t = sh[0];
#pragma unroll
        for (int i = 1; i < 8; i++) t = fmaxf(t, sh[i]);
        atomicMax(&g_wamax[slot], __float_as_uint(t));
    }
}

template <int PHASE>
__global__ void quant_w_kernel(const float* __restrict__ w, int n2) {
    __nv_bfloat16* qw = (PHASE == 0) ? g_qw1 : g_qw2;
    const float s = fmaxf(__uint_as_float(g_wamax[PHASE]), 1e-6f) / 127.0f;
    __nv_bfloat162* q2 = (__nv_bfloat162*)qw;      // mine: 4B stores OK
    for (int i = blockIdx.x * blockDim.x + threadIdx.x; i < n2; i += gridDim.x * blockDim.x) {
        float a = w[2 * i], b = w[2 * i + 1];      // scalar harness reads
        __nv_bfloat162 v;
        v.x = __float2bfloat16(rintf(a / s));
        v.y = __float2bfloat16(rintf(b / s));
        q2[i] = v;
    }
}

__global__ void quant_x_kernel(const float* __restrict__ x) {
    int row = blockIdx.x;
    const float* xr = x + (size_t)row * D_DIM;
    float m = 0.f;
    for (int i = threadIdx.x; i < D_DIM; i += 256) m = fmaxf(m, fabsf(xr[i]));  // scalar
    __shared__ float sh[8];
    __shared__ float s_bcast;
    int lane = threadIdx.x & 31, wid = threadIdx.x >> 5;
    m = warpMax(m);
    if (lane == 0) sh[wid] = m;
    __syncthreads();
    if (threadIdx.x == 0) {
        float t = sh[0];
#pragma unroll
        for (int i = 1; i < 8; i++) t = fmaxf(t, sh[i]);
        float s = fmaxf(t, 1e-6f) / 127.0f;
        s_bcast = s;
        g_sx[row] = s;
    }
    __syncthreads();
    float s = s_bcast;
    __nv_bfloat162* q2 = (__nv_bfloat162*)(g_qx + (size_t)row * D_DIM);   // mine
    for (int i = threadIdx.x; i < D_DIM / 2; i += 256) {
        float a = xr[2 * i], b = xr[2 * i + 1];    // scalar harness reads
        __nv_bfloat162 v;
        v.x = __float2bfloat16(rintf(a / s));
        v.y = __float2bfloat16(rintf(b / s));
        q2[i] = v;
    }
}

__global__ void quant_h_kernel() {
    int row = blockIdx.x;
    const float4* hr4 = (const float4*)(g_h + (size_t)row * H_DIM);       // mine: float4 OK
    float m = 0.f;
    for (int i = threadIdx.x; i < H_DIM / 4; i += 256) {
        float4 v = hr4[i];
        m = fmaxf(m, fmaxf(fmaxf(fabsf(v.x), fabsf(v.y)), fmaxf(fabsf(v.z), fabsf(v.w))));
    }
    __shared__ float sh[8];
    __shared__ float s_bcast;
    int lane = threadIdx.x & 31, wid = threadIdx.x >> 5;
    m = warpMax(m);
    if (lane == 0) sh[wid] = m;
    __syncthreads();
    if (threadIdx.x == 0) {
        float t = sh[0];
#pragma unroll
        for (int i = 1; i < 8; i++) t = fmaxf(t, sh[i]);
        float s = fmaxf(t, 1e-6f) / 127.0f;
        s_bcast = s;
        g_sh[row] = s;
    }
    __syncthreads();
    float s = s_bcast;
    uint2* q4 = (uint2*)(g_qh + (size_t)row * H_DIM);                     // mine: 8B stores OK
    for (int i = threadIdx.x; i < H_DIM / 4; i += 256) {
        float4 v = hr4[i];
        __nv_bfloat162 lo, hi;
        lo.x = __float2bfloat16(rintf(v.x / s));
        lo.y = __float2bfloat16(rintf(v.y / s));
        hi.x = __float2bfloat16(rintf(v.z / s));
        hi.y = __float2bfloat16(rintf(v.w / s));
        uint2 o;
        o.x = *(uint32_t*)&lo;
        o.y = *(uint32_t*)&hi;
        q4[i] = o;
    }
}

// ---------------- GEMM: R14 skeleton; ONLY fragment loads changed to ldmatrix ----------------
// block tile 128x128x64, 8 warps (2x4), warp tile 64x32, mma.sync m16n8k16.
// 3-stage cp.async pipeline, ONE __syncthreads per k-tile.
// ldmatrix.x4 (A) / .x2 (B): 8 shared-load instructions per warp per k16 vs 24.
// Bank check (144B row stride): 8 consecutive rows start at banks 4r -> 16B rows
// tile all 32 banks exactly once per phase -> conflict-free.
#define BM 128
#define BN 128
#define BK 64
#define SK 72                   // row stride 144B
#define STAGE_B (2 * BM * SK * 2)     // 36864 B
#define GSMEM   (3 * STAGE_B)         // 110592 B

template <bool GELU, int PHASE>
__global__ void __launch_bounds__(256, 2) gemm_kernel(const float* __restrict__ bias,
                                                      float* __restrict__ Cout, int M) {
    const int N = (PHASE == 0) ? H_DIM : D_DIM;
    const int K = (PHASE == 0) ? D_DIM : H_DIM;
    const __nv_bfloat16* __restrict__ A = (PHASE == 0) ? g_qx : g_qh;
    const __nv_bfloat16* __restrict__ B = (PHASE == 0) ? g_qw1 : g_qw2;
    const float* __restrict__ rowscale  = (PHASE == 0) ? g_sx : g_sh;
    float* __restrict__ C               = (PHASE == 0) ? g_h : Cout;

    extern __shared__ __align__(128) char dsm[];

    const int tid  = threadIdx.x;
    const int lane = tid & 31, warp = tid >> 5;
    const int wm = warp & 1, wn = warp >> 1;   // 2 warps in M, 4 in N
    const int bm = blockIdx.y * BM, bn = blockIdx.x * BN;

    float acc[4][4][4];
#pragma unroll
    for (int i = 0; i < 4; i++)
#pragma unroll
        for (int j = 0; j < 4; j++)
#pragma unroll
            for (int r = 0; r < 4; r++) acc[i][j][r] = 0.f;

    auto tileA = [&](int st) { return (__nv_bfloat16*)(dsm + st * STAGE_B); };
    auto tileB = [&](int st) { return (__nv_bfloat16*)(dsm + st * STAGE_B + BM * SK * 2); };

    auto load_stage = [&](int st, int k0) {
        __nv_bfloat16* sA = tileA(st);
        __nv_bfloat16* sB = tileB(st);
#pragma unroll
        for (int j = 0; j < 8; j++) {                // 2048 chunks of 16B
            int idx = tid + j * 256;
            int r = (idx >> 3) & 127, c = idx & 7;   // 8 chunks of 8 bf16 per 64-wide row
            bool isA = idx < 1024;
            const __nv_bfloat16* src = (isA ? A + (size_t)(bm + r) * K
                                            : B + (size_t)(bn + r) * K) + k0 + c * 8;
            __nv_bfloat16* dst = (isA ? sA : sB) + r * SK + c * 8;
            cp16(dst, src);
        }
        asm volatile("cp.async.commit_group;");
    };

    const int ktiles = K / BK;
    load_stage(0, 0);
    load_stage(1, BK);

    const int lrow = lane >> 2;
    const int lcol = (lane & 3) << 1;
    // ldmatrix per-lane byte offsets within a stage tile (row stride 144B)
    const uint32_t a_lane = (uint32_t)((lane & 15) * (SK * 2) + (lane >> 4) * 16);
    const uint32_t b_lane = (uint32_t)((lane & 7) * (SK * 2) + ((lane >> 3) & 1) * 16);

    for (int kt = 0; kt < ktiles; ++kt) {
        asm volatile("cp.async.wait_group 1;" ::: "memory");
        __syncthreads();

        if (kt + 2 < ktiles) load_stage((kt + 2) % 3, (kt + 2) * BK);
        else asm volatile("cp.async.commit_group;");   // empty group keeps count aligned

        const int st = kt % 3;
        const uint32_t saddr = s2u(tileA(st));
        const uint32_t baddr = s2u(tileB(st));

#pragma unroll
        for (int kk = 0; kk < BK; kk += 16) {
            uint32_t af[4][4], bf[4][2];
#pragma unroll
            for (int mi = 0; mi < 4; mi++) {
                uint32_t addr = saddr + (uint32_t)((wm * 64 + mi * 16) * (SK * 2) + kk * 2)
                                      + a_lane;
                asm volatile("ldmatrix.sync.aligned.m8n8.x4.shared.b16 {%0,%1,%2,%3}, [%4];"
                             : "=r"(af[mi][0]), "=r"(af[mi][1]),
                               "=r"(af[mi][2]), "=r"(af[mi][3])
                             : "r"(addr));
            }
#pragma unroll
            for (int ni = 0; ni < 4; ni++) {
                uint32_t addr = baddr + (uint32_t)((wn * 32 + ni * 8) * (SK * 2) + kk * 2)
                                      + b_lane;
                asm volatile("ldmatrix.sync.aligned.m8n8.x2.shared.b16 {%0,%1}, [%2];"
                             : "=r"(bf[ni][0]), "=r"(bf[ni][1]) : "r"(addr));
            }
#pragma unroll
            for (int mi = 0; mi < 4; mi++)
#pragma unroll
                for (int ni = 0; ni < 4; ni++) {
                    asm volatile(
                        "mma.sync.aligned.m16n8k16.row.col.f32.bf16.bf16.f32 "
                        "{%0,%1,%2,%3}, {%4,%5,%6,%7}, {%8,%9}, {%0,%1,%2,%3};"
                        : "+f"(acc[mi][ni][0]), "+f"(acc[mi][ni][1]),
                          "+f"(acc[mi][ni][2]), "+f"(acc[mi][ni][3])
                        : "r"(af[mi][0]), "r"(af[mi][1]), "r"(af[mi][2]), "r"(af[mi][3]),
                          "r"(bf[ni][0]), "r"(bf[ni][1]));
                }
        }
    }
    asm volatile("cp.async.wait_group 0;" ::: "memory");   // drain before exit

    // epilogue: (acc + bias) * (rowscale * sw)  [+ exact GELU]  (R14-proven)
    const float sw = fmaxf(__uint_as_float(g_wamax[PHASE]), 1e-6f) / 127.0f;
#pragma unroll
    for (int mi = 0; mi < 4; mi++) {
#pragma unroll
        for (int h = 0; h < 2; h++) {
            int row = bm + wm * 64 + mi * 16 + lrow + h * 8;
            if (row < M) {
                float rs = rowscale[row] * sw;
#pragma unroll
                for (int ni = 0; ni < 4; ni++) {
                    int col = bn + wn * 32 + ni * 8 + lcol;
                    float v0 = (acc[mi][ni][h * 2 + 0] + bias[col    ]) * rs;
                    float v1 = (acc[mi][ni][h * 2 + 1] + bias[col + 1]) * rs;
                    if (GELU) { v0 = gelu_exact(v0); v1 = gelu_exact(v1); }
                    if (PHASE == 0) {
                        float2 o = {v0, v1};
                        *(float2*)(C + (size_t)row * N + col) = o;   // g_h: mine
                    } else {
                        C[(size_t)row * N + col    ] = v0;           // d_out: scalar
                        C[(size_t)row * N + col + 1] = v1;
                    }
                }
            }
        }
    }
}

// ---------------- launch ----------------
// ncu -s 5 has a +2 harness-launch offset -> profiles MY index 3 (gemm1).
extern "C" void kernel_launch(void* const* d_in, const int* in_sizes, int n_in,
                              void* d_out, int out_size) {
    const float* x  = (const float*)d_in[0];
    const float* w1 = (const float*)d_in[1];
    const float* b1 = (const float*)d_in[2];
    const float* w2 = (const float*)d_in[3];
    const float* b2 = (const float*)d_in[4];
    const int M = in_sizes[0] / D_DIM;   // 12608

    cudaFuncSetAttribute(gemm_kernel<true, 0>,
                         cudaFuncAttributeMaxDynamicSharedMemorySize, GSMEM);
    cudaFuncSetAttribute(gemm_kernel<false, 1>,
                         cudaFuncAttributeMaxDynamicSharedMemorySize, GSMEM);

    wamax_kernel<<<1024, 256>>>(w1, in_sizes[1], 0);           // 0
    quant_w_kernel<0><<<2048, 256>>>(w1, in_sizes[1] / 2);     // 1
    quant_x_kernel<<<M, 256>>>(x);                             // 2

    dim3 g1(H_DIM / BN, (M + BM - 1) / BM);
    gemm_kernel<true, 0><<<g1, 256, GSMEM>>>(b1, nullptr, M);  // 3  <- ncu target

    wamax_kernel<<<1024, 256>>>(w2, in_sizes[3], 1);           // 4
    quant_w_kernel<1><<<2048, 256>>>(w2, in_sizes[3] / 2);     // 5
    quant_h_kernel<<<M, 256>>>();                              // 6

    dim3 g2(D_DIM / BN, (M + BM - 1) / BM);
    gemm_kernel<false, 1><<<g2, 256, GSMEM>>>(b2, (float*)d_out, M);  // 7
}

// round 16
// speedup vs baseline: 2.0989x; 1.0246x over previous
#include <cuda_runtime.h>
#include <cuda_bf16.h>
#include <stdint.h>

// Problem dims (fixed by dataset): B=64,S=197 -> M=12608 tokens, D=768, H=3072
#define M_TOK 12608
#define M_PAD 12672           // 99 * 128
#define D_DIM 768
#define H_DIM 3072

// ---------------- scratch (device globals; zero-initialized at load) ----------------
// Vector access allowed ONLY on these aligned globals; harness pointers stay scalar.
__device__ __align__(256) __nv_bfloat16 g_qx [(size_t)M_PAD * D_DIM];   // pad rows stay 0
__device__ __align__(256) __nv_bfloat16 g_qh [(size_t)M_PAD * H_DIM];   // pad rows stay 0
__device__ __align__(256) __nv_bfloat16 g_qw1[(size_t)H_DIM * D_DIM];
__device__ __align__(256) __nv_bfloat16 g_qw2[(size_t)D_DIM * H_DIM];
__device__ __align__(256) float         g_h  [(size_t)M_TOK * H_DIM];   // fp32 post-GELU hidden
__device__ float         g_sx [M_TOK];
__device__ float         g_sh [M_TOK];
__device__ unsigned      g_hmax[M_TOK];           // row amax of gelu(h), float bits; zeroed each run
__device__ unsigned      g_wamax[2];              // zero-init; atomicMax idempotent

// ---------------- helpers ----------------
__device__ __forceinline__ float warpMax(float v) {
#pragma unroll
    for (int o = 16; o > 0; o >>= 1) v = fmaxf(v, __shfl_xor_sync(0xffffffffu, v, o));
    return v;
}

__device__ __forceinline__ float gelu_exact(float v) {
    return 0.5f * v * (1.0f + erff(v * 0.7071067811865475f));
}

__device__ __forceinline__ void cp16(void* sm, const void* gm) {
    unsigned a = (unsigned)__cvta_generic_to_shared(sm);
    asm volatile("cp.async.cg.shared.global [%0], [%1], 16;" :: "r"(a), "l"(gm));
}

__device__ __forceinline__ uint32_t s2u(const void* p) {
    return (uint32_t)__cvta_generic_to_shared(p);
}

// ---------------- elementwise kernels ----------------
__global__ void wamax_kernel(const float* __restrict__ w, int n, int slot) {
    float m = 0.f;
    for (int i = blockIdx.x * blockDim.x + threadIdx.x; i < n; i += gridDim.x * blockDim.x)
        m = fmaxf(m, fabsf(w[i]));                 // scalar harness reads
    __shared__ float sh[8];
    int lane = threadIdx.x & 31, wid = threadIdx.x >> 5;
    m = warpMax(m);
    if (lane == 0) sh[wid] = m;
    __syncthreads();
    if (threadIdx.x == 0) {
        float t = sh[0];
#pragma unroll
        for (int i = 1; i < 8; i++) t = fmaxf(t, sh[i]);
        atomicMax(&g_wamax[slot], __float_as_uint(t));
    }
}

template <int PHASE>
__global__ void quant_w_kernel(const float* __restrict__ w, int n2) {
    __nv_bfloat16* qw = (PHASE == 0) ? g_qw1 : g_qw2;
    const float s = fmaxf(__uint_as_float(g_wamax[PHASE]), 1e-6f) / 127.0f;
    __nv_bfloat162* q2 = (__nv_bfloat162*)qw;      // mine: 4B stores OK
    for (int i = blockIdx.x * blockDim.x + threadIdx.x; i < n2; i += gridDim.x * blockDim.x) {
        float a = w[2 * i], b = w[2 * i + 1];      // scalar harness reads
        __nv_bfloat162 v;
        v.x = __float2bfloat16(rintf(a / s));
        v.y = __float2bfloat16(rintf(b / s));
        q2[i] = v;
    }
}

__global__ void quant_x_kernel(const float* __restrict__ x) {
    int row = blockIdx.x;
    if (threadIdx.x == 0) g_hmax[row] = 0u;        // reset fused-amax accumulator each run
    const float* xr = x + (size_t)row * D_DIM;
    float m = 0.f;
    for (int i = threadIdx.x; i < D_DIM; i += 256) m = fmaxf(m, fabsf(xr[i]));  // scalar
    __shared__ float sh[8];
    __shared__ float s_bcast;
    int lane = threadIdx.x & 31, wid = threadIdx.x >> 5;
    m = warpMax(m);
    if (lane == 0) sh[wid] = m;
    __syncthreads();
    if (threadIdx.x == 0) {
        float t = sh[0];
#pragma unroll
        for (int i = 1; i < 8; i++) t = fmaxf(t, sh[i]);
        float s = fmaxf(t, 1e-6f) / 127.0f;
        s_bcast = s;
        g_sx[row] = s;
    }
    __syncthreads();
    float s = s_bcast;
    __nv_bfloat162* q2 = (__nv_bfloat162*)(g_qx + (size_t)row * D_DIM);   // mine
    for (int i = threadIdx.x; i < D_DIM / 2; i += 256) {
        float a = xr[2 * i], b = xr[2 * i + 1];    // scalar harness reads
        __nv_bfloat162 v;
        v.x = __float2bfloat16(rintf(a / s));
        v.y = __float2bfloat16(rintf(b / s));
        q2[i] = v;
    }
}

// single-pass: amax already accumulated by gemm1 epilogue into g_hmax
__global__ void quant_h_kernel() {
    int row = blockIdx.x;
    float s = fmaxf(__uint_as_float(g_hmax[row]), 1e-6f) / 127.0f;
    if (threadIdx.x == 0) g_sh[row] = s;
    const float4* hr4 = (const float4*)(g_h + (size_t)row * H_DIM);       // mine: float4 OK
    uint2* q4 = (uint2*)(g_qh + (size_t)row * H_DIM);                     // mine: 8B stores OK
    for (int i = threadIdx.x; i < H_DIM / 4; i += 256) {
        float4 v = hr4[i];
        __nv_bfloat162 lo, hi;
        lo.x = __float2bfloat16(rintf(v.x / s));
        lo.y = __float2bfloat16(rintf(v.y / s));
        hi.x = __float2bfloat16(rintf(v.z / s));
        hi.y = __float2bfloat16(rintf(v.w / s));
        uint2 o;
        o.x = *(uint32_t*)&lo;
        o.y = *(uint32_t*)&hi;
        q4[i] = o;
    }
}

// ---------------- GEMM: R15 skeleton; B ldmatrix.x4 pairing + fused amax epilogue ----------------
#define BM 128
#define BN 128
#define BK 64
#define SK 72                   // row stride 144B: conflict-free ldmatrix phases
#define STAGE_B (2 * BM * SK * 2)     // 36864 B
#define GSMEM   (3 * STAGE_B)         // 110592 B

template <bool GELU, int PHASE>
__global__ void __launch_bounds__(256, 2) gemm_kernel(const float* __restrict__ bias,
                                                      float* __restrict__ Cout, int M) {
    const int N = (PHASE == 0) ? H_DIM : D_DIM;
    const int K = (PHASE == 0) ? D_DIM : H_DIM;
    const __nv_bfloat16* __restrict__ A = (PHASE == 0) ? g_qx : g_qh;
    const __nv_bfloat16* __restrict__ B = (PHASE == 0) ? g_qw1 : g_qw2;
    const float* __restrict__ rowscale  = (PHASE == 0) ? g_sx : g_sh;
    float* __restrict__ C               = (PHASE == 0) ? g_h : Cout;

    extern __shared__ __align__(128) char dsm[];

    const int tid  = threadIdx.x;
    const int lane = tid & 31, warp = tid >> 5;
    const int wm = warp & 1, wn = warp >> 1;   // 2 warps in M, 4 in N
    const int bm = blockIdx.y * BM, bn = blockIdx.x * BN;

    float acc[4][4][4];
#pragma unroll
    for (int i = 0; i < 4; i++)
#pragma unroll
        for (int j = 0; j < 4; j++)
#pragma unroll
            for (int r = 0; r < 4; r++) acc[i][j][r] = 0.f;

    auto tileA = [&](int st) { return (__nv_bfloat16*)(dsm + st * STAGE_B); };
    auto tileB = [&](int st) { return (__nv_bfloat16*)(dsm + st * STAGE_B + BM * SK * 2); };

    auto load_stage = [&](int st, int k0) {
        __nv_bfloat16* sA = tileA(st);
        __nv_bfloat16* sB = tileB(st);
#pragma unroll
        for (int j = 0; j < 8; j++) {                // 2048 chunks of 16B
            int idx = tid + j * 256;
            int r = (idx >> 3) & 127, c = idx & 7;
            bool isA = idx < 1024;
            const __nv_bfloat16* src = (isA ? A + (size_t)(bm + r) * K
                                            : B + (size_t)(bn + r) * K) + k0 + c * 8;
            __nv_bfloat16* dst = (isA ? sA : sB) + r * SK + c * 8;
            cp16(dst, src);
        }
        asm volatile("cp.async.commit_group;");
    };

    const int ktiles = K / BK;
    load_stage(0, 0);
    load_stage(1, BK);

    const int lrow = lane >> 2;
    const int lcol = (lane & 3) << 1;
    // A ldmatrix.x4 per-lane offset (rows 0-15, +16B half-column)
    const uint32_t a_lane = (uint32_t)((lane & 15) * (SK * 2) + (lane >> 4) * 16);
    // B ldmatrix.x4 per-lane offset: lanes 0-7 m0 rows, 8-15 m1(+16B col),
    // 16-23 m2(+8 rows), 24-31 m3(+8 rows,+16B col)
    const uint32_t b4_lane = (uint32_t)((lane & 7) * (SK * 2) + ((lane >> 3) & 1) * 16
                                        + (lane >> 4) * 8 * (SK * 2));

    for (int kt = 0; kt < ktiles; ++kt) {
        asm volatile("cp.async.wait_group 1;" ::: "memory");
        __syncthreads();

        if (kt + 2 < ktiles) load_stage((kt + 2) % 3, (kt + 2) * BK);
        else asm volatile("cp.async.commit_group;");

        const int st = kt % 3;
        const uint32_t saddr = s2u(tileA(st));
        const uint32_t baddr = s2u(tileB(st));

#pragma unroll
        for (int kk = 0; kk < BK; kk += 16) {
            uint32_t af[4][4], bf[4][2];
#pragma unroll
            for (int mi = 0; mi < 4; mi++) {
                uint32_t addr = saddr + (uint32_t)((wm * 64 + mi * 16) * (SK * 2) + kk * 2)
                                      + a_lane;
                asm volatile("ldmatrix.sync.aligned.m8n8.x4.shared.b16 {%0,%1,%2,%3}, [%4];"
                             : "=r"(af[mi][0]), "=r"(af[mi][1]),
                               "=r"(af[mi][2]), "=r"(af[mi][3])
                             : "r"(addr));
            }
#pragma unroll
            for (int nj = 0; nj < 2; nj++) {         // pairs (2nj, 2nj+1) in one x4
                uint32_t addr = baddr + (uint32_t)((wn * 32 + nj * 16) * (SK * 2) + kk * 2)
                                      + b4_lane;
                asm volatile("ldmatrix.sync.aligned.m8n8.x4.shared.b16 {%0,%1,%2,%3}, [%4];"
                             : "=r"(bf[2 * nj][0]), "=r"(bf[2 * nj][1]),
                               "=r"(bf[2 * nj + 1][0]), "=r"(bf[2 * nj + 1][1])
                             : "r"(addr));
            }
#pragma unroll
            for (int mi = 0; mi < 4; mi++)
#pragma unroll
                for (int ni = 0; ni < 4; ni++) {
                    asm volatile(
                        "mma.sync.aligned.m16n8k16.row.col.f32.bf16.bf16.f32 "
                        "{%0,%1,%2,%3}, {%4,%5,%6,%7}, {%8,%9}, {%0,%1,%2,%3};"
                        : "+f"(acc[mi][ni][0]), "+f"(acc[mi][ni][1]),
                          "+f"(acc[mi][ni][2]), "+f"(acc[mi][ni][3])
                        : "r"(af[mi][0]), "r"(af[mi][1]), "r"(af[mi][2]), "r"(af[mi][3]),
                          "r"(bf[ni][0]), "r"(bf[ni][1]));
                }
        }
    }
    asm volatile("cp.async.wait_group 0;" ::: "memory");

    // epilogue: (acc + bias) * (rowscale * sw)  [+ exact GELU + fused row-amax]
    const float sw = fmaxf(__uint_as_float(g_wamax[PHASE]), 1e-6f) / 127.0f;
#pragma unroll
    for (int mi = 0; mi < 4; mi++) {
#pragma unroll
        for (int h = 0; h < 2; h++) {
            int row = bm + wm * 64 + mi * 16 + lrow + h * 8;
            const bool ok = (row < M);
            float rs = ok ? rowscale[row] * sw : 0.f;
            float vv[4][2];
            float lm = 0.f;
#pragma unroll
            for (int ni = 0; ni < 4; ni++) {
                int col = bn + wn * 32 + ni * 8 + lcol;
                float v0 = (acc[mi][ni][h * 2 + 0] + bias[col    ]) * rs;
                float v1 = (acc[mi][ni][h * 2 + 1] + bias[col + 1]) * rs;
                if (GELU) {
                    v0 = gelu_exact(v0);
                    v1 = gelu_exact(v1);
                    lm = fmaxf(lm, fmaxf(fabsf(v0), fabsf(v1)));
                }
                vv[ni][0] = v0;
                vv[ni][1] = v1;
            }
            if (GELU) {   // quad-level reduce (lanes 4k..4k+3 share row), full-mask shfl
                lm = fmaxf(lm, __shfl_xor_sync(0xffffffffu, lm, 1));
                lm = fmaxf(lm, __shfl_xor_sync(0xffffffffu, lm, 2));
                if (ok && (lane & 3) == 0) atomicMax(&g_hmax[row], __float_as_uint(lm));
            }
            if (ok) {
#pragma unroll
                for (int ni = 0; ni < 4; ni++) {
                    int col = bn + wn * 32 + ni * 8 + lcol;
                    if (PHASE == 0) {
                        float2 o = {vv[ni][0], vv[ni][1]};
                        *(float2*)(C + (size_t)row * N + col) = o;   // g_h: mine
                    } else {
                        C[(size_t)row * N + col    ] = vv[ni][0];    // d_out: scalar
                        C[(size_t)row * N + col + 1] = vv[ni][1];
                    }
                }
            }
        }
    }
}

// ---------------- launch ----------------
// ncu -s 5 has a +2 harness-launch offset -> profiles MY index 3 (gemm1).
extern "C" void kernel_launch(void* const* d_in, const int* in_sizes, int n_in,
                              void* d_out, int out_size) {
    const float* x  = (const float*)d_in[0];
    const float* w1 = (const float*)d_in[1];
    const float* b1 = (const float*)d_in[2];
    const float* w2 = (const float*)d_in[3];
    const float* b2 = (const float*)d_in[4];
    const int M = in_sizes[0] / D_DIM;   // 12608

    cudaFuncSetAttribute(gemm_kernel<true, 0>,
                         cudaFuncAttributeMaxDynamicSharedMemorySize, GSMEM);
    cudaFuncSetAttribute(gemm_kernel<false, 1>,
                         cudaFuncAttributeMaxDynamicSharedMemorySize, GSMEM);

    wamax_kernel<<<1024, 256>>>(w1, in_sizes[1], 0);           // 0
    quant_w_kernel<0><<<2048, 256>>>(w1, in_sizes[1] / 2);     // 1
    quant_x_kernel<<<M, 256>>>(x);                             // 2 (also zeroes g_hmax)

    dim3 g1(H_DIM / BN, (M + BM - 1) / BM);
    gemm_kernel<true, 0><<<g1, 256, GSMEM>>>(b1, nullptr, M);  // 3  <- ncu target

    wamax_kernel<<<1024, 256>>>(w2, in_sizes[3], 1);           // 4
    quant_w_kernel<1><<<2048, 256>>>(w2, in_sizes[3] / 2);     // 5
    quant_h_kernel<<<M, 256>>>();                              // 6 (single pass)

    dim3 g2(D_DIM / BN, (M + BM - 1) / BM);
    gemm_kernel<false, 1><<<g2, 256, GSMEM>>>(b2, (float*)d_out, M);  // 7
}